// round 1
// baseline (speedup 1.0000x reference)
#include <cuda_runtime.h>

#define BATCH 32
#define CH    64
#define HH    224
#define WW    224
#define TW    32          // tile width in pixels (16 pixel-pairs)
#define TH    8           // tile height
#define CIC   4           // input-channel chunk staged in smem
#define XPITCH 36         // padded smem row pitch (34 used + 2 pad)
#define XROWS (TH + 2)    // rows incl. halo

// Pre-binarized weights, layout [ci][tap][coPair] as float4 {s(co),s(co),s(co+1),s(co+1)}
// so one LDS.128 broadcast feeds two fma.rn.f32x2 without repacking.
__device__ float4 g_w4[CH * 9 * (CH / 2)];   // 18432 float4 = 288 KB

__global__ void prep_weights(const float* __restrict__ w) {
    int idx = blockIdx.x * blockDim.x + threadIdx.x;
    const int total = CH * 9 * (CH / 2);
    if (idx >= total) return;
    int coPair = idx & 31;
    int tap    = (idx >> 5) % 9;
    int ci     = idx / (9 * 32);
    int co     = coPair * 2;
    float w0 = w[(co * CH + ci) * 9 + tap];         // weight[co][ci][kh][kw], tap=kh*3+kw
    float w1 = w[((co + 1) * CH + ci) * 9 + tap];
    float s0 = (w0 > 0.f) ? 1.f : ((w0 < 0.f) ? -1.f : 0.f);
    float s1 = (w1 > 0.f) ? 1.f : ((w1 < 0.f) ? -1.f : 0.f);
    g_w4[idx] = make_float4(s0, s0, s1, s1);
}

__device__ __forceinline__ unsigned long long pk(float lo, float hi) {
    unsigned long long r;
    asm("mov.b64 %0, {%1, %2};" : "=l"(r) : "f"(lo), "f"(hi));
    return r;
}

// Blackwell packed fp32 FMA: 2 FMAs/lane/instr (FFMA2 in SASS) — only via PTX.
__device__ __forceinline__ void ffma2(unsigned long long& d,
                                      unsigned long long a,
                                      unsigned long long b) {
    asm("fma.rn.f32x2 %0, %1, %2, %0;" : "+l"(d) : "l"(a), "l"(b));
}

__global__ __launch_bounds__(256, 2)
void bconv_kernel(const float* __restrict__ x,
                  const float* __restrict__ bias,
                  float* __restrict__ out) {
    __shared__ float  xsm[CIC * XROWS * XPITCH];   // 5.8 KB
    __shared__ float4 wsm[CIC * 9 * 32];           // 18.4 KB

    const int n  = blockIdx.z;
    const int x0 = blockIdx.x * TW;
    const int y0 = blockIdx.y * TH;

    const int tid = threadIdx.x;          // 256 threads
    const int cog = tid >> 7;             // cout group: 0 -> co 0..31, 1 -> co 32..63
    const int t   = tid & 127;
    const int tx  = t & 15;               // pixel-pair index (covers x0 + 2*tx, +1)
    const int py  = t >> 4;               // row within tile
    const int cobase = cog * 32;

    // 32 packed accumulators: acc[j] = (out[px0], out[px1]) for co = cobase + j
    unsigned long long acc[32];
#pragma unroll
    for (int j = 0; j < 32; j++) {
        float bv = bias[cobase + j];
        acc[j] = pk(bv, bv);
    }

    const float* xn = x + (long long)n * CH * HH * WW;

    for (int ci0 = 0; ci0 < CH; ci0 += CIC) {
        __syncthreads();
        // stage binarized weights for this ci chunk (contiguous in g_w4)
        const float4* gw = g_w4 + ci0 * 9 * 32;
        for (int i = tid; i < CIC * 9 * 32; i += 256)
            wsm[i] = gw[i];
        // stage input tile with zero-filled halo (handles pad=1 branch-free)
        for (int i = tid; i < CIC * XROWS * XPITCH; i += 256) {
            int ci  = i / (XROWS * XPITCH);
            int rem = i - ci * (XROWS * XPITCH);
            int r   = rem / XPITCH;
            int c   = rem - r * XPITCH;
            int gy = y0 + r - 1;
            int gx = x0 + c - 1;
            float v = 0.f;
            if (c < TW + 2 && gy >= 0 && gy < HH && gx >= 0 && gx < WW)
                v = xn[((ci0 + ci) * HH + gy) * WW + gx];
            xsm[i] = v;
        }
        __syncthreads();

#pragma unroll
        for (int ci = 0; ci < CIC; ci++) {
            // Build 3 rows x 3 shifted packed input pairs for this thread's pixel pair.
            // Pixel pair = (x0+2tx, x0+2tx+1); smem col of input x-coord g is (g - x0 + 1).
            unsigned long long P[3][3];
#pragma unroll
            for (int r = 0; r < 3; r++) {
                const float* row = &xsm[(ci * XROWS + py + r) * XPITCH + 2 * tx];
                float2 a = *(const float2*)(row);      // cols 2tx, 2tx+1
                float2 b = *(const float2*)(row + 2);  // cols 2tx+2, 2tx+3
                P[r][0] = pk(a.x, a.y);   // shift kw=0 (input x-1, x)
                P[r][1] = pk(a.y, b.x);   // shift kw=1
                P[r][2] = pk(b.x, b.y);   // shift kw=2
            }
#pragma unroll
            for (int r = 0; r < 3; r++) {
#pragma unroll
                for (int s = 0; s < 3; s++) {
                    const float4* wp = &wsm[(ci * 9 + r * 3 + s) * 32 + cog * 16];
                    unsigned long long xv = P[r][s];
#pragma unroll
                    for (int j2 = 0; j2 < 16; j2++) {
                        float4 wv = wp[j2];            // LDS.128 broadcast (uniform addr)
                        ffma2(acc[2 * j2],     xv, pk(wv.x, wv.y));
                        ffma2(acc[2 * j2 + 1], xv, pk(wv.z, wv.w));
                    }
                }
            }
        }
    }

    // Epilogue: 32 couts x one float2 each, coalesced across tx.
    const int y = y0 + py;
    float* op = out + (((long long)n * CH + cobase) * HH + y) * WW + x0 + 2 * tx;
#pragma unroll
    for (int j = 0; j < 32; j++) {
        *(float2*)op = *(float2*)&acc[j];
        op += HH * WW;
    }
}

extern "C" void kernel_launch(void* const* d_in, const int* in_sizes, int n_in,
                              void* d_out, int out_size) {
    const float* x    = (const float*)d_in[0];   // [32,64,224,224]
    const float* w    = (const float*)d_in[1];   // [64,64,3,3]
    const float* bias = (const float*)d_in[2];   // [64]
    float* out = (float*)d_out;                  // [32,64,224,224]

    const int wtotal = CH * 9 * (CH / 2);        // 18432
    prep_weights<<<(wtotal + 255) / 256, 256>>>(w);

    dim3 grid(WW / TW, HH / TH, BATCH);          // (7, 28, 32)
    bconv_kernel<<<grid, 256>>>(x, bias, out);
}

// round 6
// speedup vs baseline: 3.2723x; 3.2723x over previous
#include <cuda_runtime.h>
#include <cuda_bf16.h>
#include <stdint.h>

#define CH 64
#define HH 224
#define WW 224
#define HW (HH*WW)

#define TPX 32          // output tile width
#define TRY 8           // output tile rows
#define IW  34          // staged input width  (x0-1 .. x0+32)
#define IR  10          // staged input rows   (y0-1 .. y0+8)

#define W_BYTES (9*64*128)            // 73728 binarized weights [tap][co][ci]
#define P_BYTES (IR*IW*128)           // 43520 one bf16 plane [(r,q)][ci]
#define OFF_W   0u
#define OFF_PH  ((uint32_t)W_BYTES)
#define OFF_PL  ((uint32_t)(W_BYTES + P_BYTES))
#define SMEM_DYN (W_BYTES + 2*P_BYTES)   // 160768 B

// Pre-binarized weights, bf16, layout [tap][co][ci]  (row = 64 ci = 128 B)
__device__ __nv_bfloat16 g_wb[9 * 64 * 64];

__global__ void prep_weights(const float* __restrict__ w) {
    int idx = blockIdx.x * blockDim.x + threadIdx.x;
    if (idx >= 9 * 64 * 64) return;
    int ci = idx & 63, co = (idx >> 6) & 63, tap = idx >> 12;
    float v = w[(co * 64 + ci) * 9 + tap];
    float s = (v > 0.f) ? 1.f : ((v < 0.f) ? -1.f : 0.f);
    g_wb[idx] = __float2bfloat16(s);
}

__device__ __forceinline__ uint32_t smem_u32(const void* p) {
    uint32_t a;
    asm("{ .reg .u64 t; cvta.to.shared.u64 t, %1; cvt.u32.u64 %0, t; }" : "=r"(a) : "l"(p));
    return a;
}
__device__ __forceinline__ uint32_t swz(uint32_t off) {   // SW128-atom XOR swizzle
    return off ^ ((off >> 3) & 0x70);
}
__device__ __forceinline__ void sts32(uint32_t a, uint32_t v) {
    asm volatile("st.shared.b32 [%0], %1;" :: "r"(a), "r"(v));
}
__device__ __forceinline__ void sts128(uint32_t a, uint4 v) {
    asm volatile("st.shared.v4.b32 [%0], {%1,%2,%3,%4};"
                 :: "r"(a), "r"(v.x), "r"(v.y), "r"(v.z), "r"(v.w));
}
__device__ __forceinline__ void ldm_x4(uint32_t& r0, uint32_t& r1, uint32_t& r2, uint32_t& r3,
                                       uint32_t addr) {
    asm volatile("ldmatrix.sync.aligned.m8n8.x4.shared.b16 {%0,%1,%2,%3}, [%4];"
                 : "=r"(r0), "=r"(r1), "=r"(r2), "=r"(r3) : "r"(addr));
}
__device__ __forceinline__ void mma16816(float* d, uint32_t a0, uint32_t a1, uint32_t a2,
                                         uint32_t a3, uint32_t b0, uint32_t b1) {
    asm volatile("mma.sync.aligned.m16n8k16.row.col.f32.bf16.bf16.f32 "
                 "{%0,%1,%2,%3},{%4,%5,%6,%7},{%8,%9},{%0,%1,%2,%3};"
                 : "+f"(d[0]), "+f"(d[1]), "+f"(d[2]), "+f"(d[3])
                 : "r"(a0), "r"(a1), "r"(a2), "r"(a3), "r"(b0), "r"(b1));
}

__global__ void __launch_bounds__(256, 1)
bconv_mma(const float* __restrict__ x, const float* __restrict__ bias,
          float* __restrict__ out)
{
    extern __shared__ char smraw[];
    const uint32_t smb = smem_u32(smraw);
    const int tid = threadIdx.x, lane = tid & 31, wid = tid >> 5;
    const int n = blockIdx.z, x0 = blockIdx.x * TPX, y0 = blockIdx.y * TRY;

    // ---- stage binarized weights: 4608 x 16B, swizzled ----
    const uint4* gw4 = (const uint4*)g_wb;
    for (int i = tid; i < 4608; i += 256)
        sts128(smb + OFF_W + swz((uint32_t)i * 16u), __ldg(gw4 + i));

    // ---- stage input hi/lo bf16 planes: (10 rows x 34 px) x 32 ci-pairs ----
    const float* xn = x + (size_t)n * CH * HW;
    for (int idx = tid; idx < IR * IW * 32; idx += 256) {
        int q  = idx % IW;
        int rc = idx / IW;
        int r  = rc % IR;
        int cp = rc / IR;                 // ci pair 0..31
        int gx = x0 - 1 + q, ry = y0 - 1 + r;
        float v0 = 0.f, v1 = 0.f;
        if (gx >= 0 && gx < WW && ry >= 0 && ry < HH) {
            const float* p = xn + (size_t)(cp * 2) * HW + (size_t)ry * WW + gx;
            v0 = __ldg(p);
            v1 = __ldg(p + HW);
        }
        __nv_bfloat16 h0 = __float2bfloat16(v0), h1 = __float2bfloat16(v1);
        __nv_bfloat16 l0 = __float2bfloat16(v0 - __bfloat162float(h0));
        __nv_bfloat16 l1 = __float2bfloat16(v1 - __bfloat162float(h1));
        uint32_t hp = (uint32_t)__bfloat16_as_ushort(h0) | ((uint32_t)__bfloat16_as_ushort(h1) << 16);
        uint32_t lp = (uint32_t)__bfloat16_as_ushort(l0) | ((uint32_t)__bfloat16_as_ushort(l1) << 16);
        uint32_t off = (uint32_t)(r * IW + q) * 128u + (uint32_t)cp * 4u;
        uint32_t so = swz(off);
        sts32(smb + OFF_PH + so, hp);
        sts32(smb + OFF_PL + so, lp);
    }
    __syncthreads();

    // ---- warp tiling: 4(M) x 2(N); warp tile M64 x N32 ----
    const int wn = wid & 1;          // co half
    const int wm = wid >> 1;         // pixel quarter (covers rows 2wm,2wm+1 x 32px)

    // per-fragment pixel row base (pixel chunk = 16 consecutive x of one row)
    uint32_t arowb[4];
#pragma unroll
    for (int f = 0; f < 4; f++) {
        int cc = wm * 4 + f;
        int yf = cc >> 1;                       // output row in tile
        int xxf = (cc & 1) * 16 + (lane & 15);  // lane's pixel x in tile
        arowb[f] = (uint32_t)(yf * IW + xxf) * 128u;
    }
    const uint32_t acol = ((uint32_t)lane >> 4) * 16u;            // k-halves for A
    const uint32_t bco0 = (uint32_t)(wn * 32 + ((lane >> 4) << 3) + (lane & 7));
    const uint32_t bkb  = (((uint32_t)lane >> 3) & 1u) * 16u;     // k-halves for B

    float acc[4][4][4];
#pragma unroll
    for (int f = 0; f < 4; f++)
#pragma unroll
        for (int g = 0; g < 4; g++)
#pragma unroll
            for (int r = 0; r < 4; r++) acc[f][g][r] = 0.f;

    for (int t = 0; t < 9; t++) {
        const int kh = t / 3, kw = t % 3;
        const uint32_t wbase = OFF_W + (uint32_t)t * 64u * 128u;
        const uint32_t shiftA = (uint32_t)(kh * IW + kw) * 128u;
#pragma unroll
        for (int c = 0; c < 4; c++) {
            // B fragments: co rows [wn*32 .. +32), k chunk c (non-trans ldmatrix, [n][k] rows)
            uint32_t b0, b1, b2, b3, b4, b5, b6, b7;
            ldm_x4(b0, b1, b2, b3, smb + wbase + swz((bco0)      * 128u + (uint32_t)c * 32u + bkb));
            ldm_x4(b4, b5, b6, b7, smb + wbase + swz((bco0 + 16) * 128u + (uint32_t)c * 32u + bkb));
            const uint32_t kofs = shiftA + (uint32_t)c * 32u + acol;
#pragma unroll
            for (int h = 0; h < 2; h++) {
                const uint32_t pb = smb + (h ? OFF_PL : OFF_PH);
#pragma unroll
                for (int f = 0; f < 4; f++) {
                    uint32_t a0, a1, a2, a3;
                    ldm_x4(a0, a1, a2, a3, pb + swz(arowb[f] + kofs));
                    mma16816(acc[f][0], a0, a1, a2, a3, b0, b1);
                    mma16816(acc[f][1], a0, a1, a2, a3, b2, b3);
                    mma16816(acc[f][2], a0, a1, a2, a3, b4, b5);
                    mma16816(acc[f][3], a0, a1, a2, a3, b6, b7);
                }
            }
        }
    }

    // ---- epilogue: bias + store (32B-sector coalesced) ----
    const int r0 = lane >> 2, c0 = (lane & 3) * 2;
    float bl[4], bh[4];
#pragma unroll
    for (int g = 0; g < 4; g++) {
        int co = wn * 32 + g * 8 + c0;
        bl[g] = __ldg(bias + co);
        bh[g] = __ldg(bias + co + 1);
    }
#pragma unroll
    for (int f = 0; f < 4; f++) {
        int cc = wm * 4 + f;
        int y = y0 + (cc >> 1);
        int xb = x0 + (cc & 1) * 16;
#pragma unroll
        for (int g = 0; g < 4; g++) {
            int co = wn * 32 + g * 8 + c0;
            float* o0 = out + (((size_t)n * CH + co)     * HH + y) * WW + xb;
            float* o1 = out + (((size_t)n * CH + co + 1) * HH + y) * WW + xb;
            o0[r0]     = acc[f][g][0] + bl[g];
            o1[r0]     = acc[f][g][1] + bh[g];
            o0[r0 + 8] = acc[f][g][2] + bl[g];
            o1[r0 + 8] = acc[f][g][3] + bh[g];
        }
    }
}

extern "C" void kernel_launch(void* const* d_in, const int* in_sizes, int n_in,
                              void* d_out, int out_size) {
    const float* x    = (const float*)d_in[0];   // [32,64,224,224]
    const float* w    = (const float*)d_in[1];   // [64,64,3,3]
    const float* bias = (const float*)d_in[2];   // [64]
    float* out = (float*)d_out;

    prep_weights<<<(9 * 64 * 64 + 255) / 256, 256>>>(w);

    cudaFuncSetAttribute(bconv_mma, cudaFuncAttributeMaxDynamicSharedMemorySize, SMEM_DYN);
    dim3 grid(WW / TPX, HH / TRY, 32);   // (7, 28, 32) = 6272 CTAs
    bconv_mma<<<grid, 256, SMEM_DYN>>>(x, bias, out);
}